// round 10
// baseline (speedup 1.0000x reference)
#include <cuda_runtime.h>
#include <cuda_bf16.h>

// SimSiam loss, algebraically reduced:
//   loss = -0.5 * sum_c( P_c . Z_c  -  sum_{i in c} pn_i.zn_i ) / npairs
// where P_c/Z_c are per-class sums of L2-normalized rows and
// npairs = sum_c m_c*(m_c-1)/2.   O(n*d) work, no 8192x8192 GEMM.
//
// SINGLE LAUNCH, SMALL PERSISTENT GRID: 128 CTAs (<=1 per SM, all
// co-resident -> spin barrier is safe), each warp loops over 8 rows.
// Vs the failed 1024-CTA fusions (R6/R8): 8x fewer gpu-scope fences at
// the barrier, and occupancy-1 means minimal cross-CTA finish-time
// spread, so the barrier wait is just the straggler delta. Per-block
// diag/pair partials live in SHARED memory across the barrier — no
// global partial arrays, no partial atomics.
//
// Pair count is incremental: atomicAdd(&cnt,1) returns old m; summing old
// m over a class's rows = m(m-1)/2.
//
// Scratch invariant: all accumulated __device__ scratch is ZERO at
// kernel_launch entry (zero at module load; phase 2 restores it).

#define NCLASS 512
#define D      128
#define EPS    1e-8f
#define NBLK   128                 // persistent CTAs (one per SM)
#define CPB    (NCLASS / NBLK)     // 4 classes per block in phase 2

__device__ float              g_P[NCLASS * D];
__device__ float              g_Z[NCLASS * D];
__device__ int                g_cnt[NCLASS];
__device__ double             g_S;
__device__ unsigned long long g_pairs;
__device__ unsigned int       g_arrive;
__device__ unsigned int       g_done;

// 128-bit reduction into global memory (sm_90+), no return value.
__device__ __forceinline__ void red_add_v4(float* p, float x, float y, float z, float w) {
    asm volatile("red.global.add.v4.f32 [%0], {%1, %2, %3, %4};"
                 :: "l"(p), "f"(x), "f"(y), "f"(z), "f"(w) : "memory");
}

__global__ void __launch_bounds__(256, 1)
simsiam_kernel(const float* __restrict__ ps,
               const float* __restrict__ zs,
               const void*  __restrict__ tgv,
               float* __restrict__ out,
               int n_rows) {
    __shared__ double       sdp[8];
    __shared__ unsigned int spr[8];
    __shared__ int          s_is64;
    __shared__ double       s_diag;
    __shared__ unsigned int s_pairs;

    int wid  = threadIdx.x >> 5;
    int lane = threadIdx.x & 31;
    int gw   = blockIdx.x * 8 + wid;       // global warp id, 0..1023
    const int TW = NBLK * 8;               // total warps = 1024

    // ---- targets dtype sniff (warp 0): first 64 int64-view slots (512 B,
    // in-bounds for either dtype; misdetect prob ~2^-576 for random labels).
    if (wid == 0) {
        const long long* t64 = (const long long*)tgv;
        int nslots = n_rows / 2;
        int k = (nslots < 64) ? nslots : 64;
        int bad = 0;
        for (int i = lane; i < k; i += 32) {
            long long v = __ldg(&t64[i]);
            if (v < 0 || v >= NCLASS) bad = 1;
        }
        bad = __any_sync(0xFFFFFFFFu, bad);
        if (lane == 0) s_is64 = !bad;
    }
    __syncthreads();
    int is64 = s_is64;

    // ---- phase 1: each warp loops over rows gw, gw+1024, ... ----
    double       diag = 0.0;
    unsigned int prow = 0u;
    for (int r = gw; r < n_rows; r += TW) {
        float4 a = reinterpret_cast<const float4*>(ps)[r * (D / 4) + lane];
        float4 b = reinterpret_cast<const float4*>(zs)[r * (D / 4) + lane];

        float sa = a.x * a.x + a.y * a.y + a.z * a.z + a.w * a.w;
        float sb = b.x * b.x + b.y * b.y + b.z * b.z + b.w * b.w;
        float dp = a.x * b.x + a.y * b.y + a.z * b.z + a.w * b.w;

        #pragma unroll
        for (int o = 16; o > 0; o >>= 1) {
            sa += __shfl_xor_sync(0xFFFFFFFFu, sa, o);
            sb += __shfl_xor_sync(0xFFFFFFFFu, sb, o);
            dp += __shfl_xor_sync(0xFFFFFFFFu, dp, o);
        }

        float invp = 1.0f / fmaxf(sqrtf(sa), EPS);
        float invz = 1.0f / fmaxf(sqrtf(sb), EPS);

        int t;
        if (is64) t = (int)reinterpret_cast<const long long*>(tgv)[r];
        else      t = reinterpret_cast<const int*>(tgv)[r];

        red_add_v4(&g_P[t * D + lane * 4], a.x * invp, a.y * invp, a.z * invp, a.w * invp);
        red_add_v4(&g_Z[t * D + lane * 4], b.x * invz, b.y * invz, b.z * invz, b.w * invz);

        if (lane == 0) {
            prow += (unsigned int)atomicAdd(&g_cnt[t], 1);
            diag += (double)(dp * invp * invz);
        }
    }
    if (lane == 0) { sdp[wid] = diag; spr[wid] = prow; }
    __syncthreads();
    if (threadIdx.x == 0) {
        s_diag  = sdp[0] + sdp[1] + sdp[2] + sdp[3]
                + sdp[4] + sdp[5] + sdp[6] + sdp[7];
        s_pairs = spr[0] + spr[1] + spr[2] + spr[3]
                + spr[4] + spr[5] + spr[6] + spr[7];
    }

    // ---- grid barrier among 128 co-resident equal-work CTAs ----
    if (threadIdx.x == 0) {
        __threadfence();                                  // publish REDs/cnt
        atomicAdd(&g_arrive, 1u);
        while (*(volatile unsigned int*)&g_arrive < NBLK) __nanosleep(32);
        __threadfence();                                  // acquire
    }
    __syncthreads();

    // ---- phase 2: 4 classes per block; threads 0..127 do the dot ----
    __shared__ double sdot[4];
    int c0 = blockIdx.x * CPB;
    if (threadIdx.x < 128) {
        int idx = c0 * (D / 4) + threadIdx.x;   // 4 classes * 32 float4 = 128
        float4 p = reinterpret_cast<const float4*>(g_P)[idx];
        float4 z = reinterpret_cast<const float4*>(g_Z)[idx];
        float dot = p.x * z.x + p.y * z.y + p.z * z.z + p.w * z.w;
        #pragma unroll
        for (int o = 16; o > 0; o >>= 1)
            dot += __shfl_xor_sync(0xFFFFFFFFu, dot, o);
        if (lane == 0) sdot[wid] = (double)dot;

        // restore launch-entry zero invariant
        float4 zero4 = make_float4(0.f, 0.f, 0.f, 0.f);
        reinterpret_cast<float4*>(g_P)[idx] = zero4;
        reinterpret_cast<float4*>(g_Z)[idx] = zero4;
    }
    if (threadIdx.x < CPB) g_cnt[c0 + threadIdx.x] = 0;
    __syncthreads();

    if (threadIdx.x == 0) {
        double s = sdot[0] + sdot[1] + sdot[2] + sdot[3] - s_diag;
        atomicAdd(&g_S, s);                               // 128 atomics total
        if (s_pairs) atomicAdd(&g_pairs, (unsigned long long)s_pairs);
        __threadfence();
        unsigned int done = atomicAdd(&g_done, 1u);
        if (done == (unsigned int)(NBLK - 1)) {
            double np = (g_pairs > 0ull) ? (double)g_pairs : 1.0;
            out[0] = (float)(-0.5 * g_S / np);
            g_S = 0.0; g_pairs = 0ull;
            g_arrive = 0u; g_done = 0u;
        }
    }
}

// ---------------------------------------------------------------------------
extern "C" void kernel_launch(void* const* d_in, const int* in_sizes, int n_in,
                              void* d_out, int out_size) {
    const float* ps  = (const float*)d_in[0];
    const float* zs  = (const float*)d_in[1];
    const void*  tgt = d_in[2];
    float*       out = (float*)d_out;

    int n_rows = in_sizes[0] / D;   // 8192

    simsiam_kernel<<<NBLK, 256>>>(ps, zs, tgt, out, n_rows);
}

// round 11
// speedup vs baseline: 1.2516x; 1.2516x over previous
#include <cuda_runtime.h>
#include <cuda_bf16.h>

// SimSiam loss, algebraically reduced:
//   loss = -0.5 * sum_c( P_c . Z_c  -  sum_{i in c} pn_i.zn_i ) / npairs
// where P_c/Z_c are per-class sums of L2-normalized rows and
// npairs = sum_c m_c*(m_c-1)/2.   O(n*d) work, no 8192x8192 GEMM.
//
// TWO KERNELS + PDL. All in-kernel fusion variants (R6/R8/R10) measured
// ~21us vs 12.3us split: grid-wide barriers pay slowest-CTA spread and
// per-block gpu-scope fences; the persistent small-grid variant kills MLP.
// Instead, final_kernel is launched with PROGRAMMATIC STREAM SERIALIZATION:
// its CTAs are scheduled while accum still runs and block inside
// cudaGridDependencySynchronize(), hiding the ~3-5us launch latency that
// was final's dominant cost.
//
// Pair count is incremental: atomicAdd(&cnt,1) returns old m; summing old
// m over a class's rows = m(m-1)/2. final never reads g_cnt (only zeros it).
//
// Scratch invariant: all accumulated __device__ scratch is ZERO at
// kernel_launch entry (zero at module load; final_kernel restores it).

#define NCLASS 512
#define D      128
#define EPS    1e-8f
#define FBLK   64          // final_kernel grid size / partial-slot count

__device__ float              g_P[NCLASS * D];
__device__ float              g_Z[NCLASS * D];
__device__ int                g_cnt[NCLASS];
__device__ double             g_Dpart[FBLK];     // diag partials
__device__ unsigned long long g_PairPart[FBLK];  // incremental pair partials
__device__ double             g_S;
__device__ unsigned long long g_pairs;
__device__ unsigned int       g_done;

// 128-bit reduction into global memory (sm_90+), no return value.
__device__ __forceinline__ void red_add_v4(float* p, float x, float y, float z, float w) {
    asm volatile("red.global.add.v4.f32 [%0], {%1, %2, %3, %4};"
                 :: "l"(p), "f"(x), "f"(y), "f"(z), "f"(w) : "memory");
}

// ---------------------------------------------------------------------------
// One warp per row: float4 loads, warp-reduce norms + dot, scatter normalized
// rows into per-class sums with 128-bit vector atomics. In-block dtype sniff:
// warp 0 reads the first 64 int64-view slots (512 B, in-bounds either way);
// an int32 buffer misdetects only if 64 consecutive odd labels are 0.
__global__ void accum_kernel(const float* __restrict__ ps,
                             const float* __restrict__ zs,
                             const void*  __restrict__ tgv,
                             int n_rows) {
    __shared__ double       sdp[8];
    __shared__ unsigned int spr[8];
    __shared__ int          s_is64;

    int warp_in_blk = threadIdx.x >> 5;
    int lane        = threadIdx.x & 31;
    int warp        = (blockIdx.x * blockDim.x + threadIdx.x) >> 5;

    if (warp_in_blk == 0) {
        const long long* t64 = (const long long*)tgv;
        int nslots = n_rows / 2;
        int k = (nslots < 64) ? nslots : 64;
        int bad = 0;
        for (int i = lane; i < k; i += 32) {
            long long v = __ldg(&t64[i]);
            if (v < 0 || v >= NCLASS) bad = 1;
        }
        bad = __any_sync(0xFFFFFFFFu, bad);
        if (lane == 0) s_is64 = !bad;
    }
    __syncthreads();
    int is64 = s_is64;

    double       diag = 0.0;
    unsigned int prow = 0u;
    if (warp < n_rows) {
        float4 a = reinterpret_cast<const float4*>(ps)[warp * (D / 4) + lane];
        float4 b = reinterpret_cast<const float4*>(zs)[warp * (D / 4) + lane];

        float sa = a.x * a.x + a.y * a.y + a.z * a.z + a.w * a.w;
        float sb = b.x * b.x + b.y * b.y + b.z * b.z + b.w * b.w;
        float dp = a.x * b.x + a.y * b.y + a.z * b.z + a.w * b.w;

        #pragma unroll
        for (int o = 16; o > 0; o >>= 1) {
            sa += __shfl_xor_sync(0xFFFFFFFFu, sa, o);
            sb += __shfl_xor_sync(0xFFFFFFFFu, sb, o);
            dp += __shfl_xor_sync(0xFFFFFFFFu, dp, o);
        }

        float invp = 1.0f / fmaxf(sqrtf(sa), EPS);
        float invz = 1.0f / fmaxf(sqrtf(sb), EPS);

        int t;
        if (is64) t = (int)reinterpret_cast<const long long*>(tgv)[warp];
        else      t = reinterpret_cast<const int*>(tgv)[warp];

        red_add_v4(&g_P[t * D + lane * 4], a.x * invp, a.y * invp, a.z * invp, a.w * invp);
        red_add_v4(&g_Z[t * D + lane * 4], b.x * invz, b.y * invz, b.z * invz, b.w * invz);

        if (lane == 0) {
            prow = (unsigned int)atomicAdd(&g_cnt[t], 1);  // old m
            diag = (double)(dp * invp * invz);
        }
    }
    if (lane == 0) { sdp[warp_in_blk] = diag; spr[warp_in_blk] = prow; }
    __syncthreads();
    if (threadIdx.x == 0) {
        double s = sdp[0] + sdp[1] + sdp[2] + sdp[3]
                 + sdp[4] + sdp[5] + sdp[6] + sdp[7];
        unsigned int pr = spr[0] + spr[1] + spr[2] + spr[3]
                        + spr[4] + spr[5] + spr[6] + spr[7];
        int slot = blockIdx.x & (FBLK - 1);
        atomicAdd(&g_Dpart[slot], s);
        atomicAdd(&g_PairPart[slot], (unsigned long long)pr);
    }
}

// ---------------------------------------------------------------------------
// PDL consumer: CTAs launch while accum runs, block at the dependency sync,
// then do per-class dots (warp per class, 8/block), ONE double atomic per
// block, fold own partial slots, re-zero scratch, last-block epilogue.
__global__ void final_kernel(float* __restrict__ out) {
    __shared__ double sdot[8];

    // Non-dependent prologue (index math) before the grid sync.
    int lane = threadIdx.x & 31;
    int wid  = threadIdx.x >> 5;                 // 0..7
    int c    = blockIdx.x * 8 + wid;
    int idx  = c * (D / 4) + lane;

    // Wait for accum_kernel's writes to be visible.
    cudaGridDependencySynchronize();

    float4 p = reinterpret_cast<const float4*>(g_P)[idx];
    float4 z = reinterpret_cast<const float4*>(g_Z)[idx];
    float dot = p.x * z.x + p.y * z.y + p.z * z.z + p.w * z.w;
    #pragma unroll
    for (int o = 16; o > 0; o >>= 1)
        dot += __shfl_xor_sync(0xFFFFFFFFu, dot, o);
    if (lane == 0) sdot[wid] = (double)dot;

    // Re-zero owned scratch (restores launch-entry invariant).
    float4 zero4 = make_float4(0.f, 0.f, 0.f, 0.f);
    reinterpret_cast<float4*>(g_P)[idx] = zero4;
    reinterpret_cast<float4*>(g_Z)[idx] = zero4;
    if (threadIdx.x < 8) g_cnt[blockIdx.x * 8 + threadIdx.x] = 0;

    __syncthreads();
    if (threadIdx.x == 0) {
        double s = sdot[0] + sdot[1] + sdot[2] + sdot[3]
                 + sdot[4] + sdot[5] + sdot[6] + sdot[7]
                 - g_Dpart[blockIdx.x];
        unsigned long long pr = g_PairPart[blockIdx.x];
        g_Dpart[blockIdx.x]    = 0.0;
        g_PairPart[blockIdx.x] = 0ull;
        atomicAdd(&g_S, s);                          // 64 atomics total
        atomicAdd(&g_pairs, pr);
        __threadfence();
        unsigned int done = atomicAdd(&g_done, 1u);
        if (done == (unsigned int)(FBLK - 1)) {
            double np = (g_pairs > 0ull) ? (double)g_pairs : 1.0;
            out[0] = (float)(-0.5 * g_S / np);
            g_S = 0.0; g_pairs = 0ull; g_done = 0u;
        }
    }
}

// ---------------------------------------------------------------------------
extern "C" void kernel_launch(void* const* d_in, const int* in_sizes, int n_in,
                              void* d_out, int out_size) {
    const float* ps  = (const float*)d_in[0];
    const float* zs  = (const float*)d_in[1];
    const void*  tgt = d_in[2];
    float*       out = (float*)d_out;

    int n_rows = in_sizes[0] / D;   // 8192

    accum_kernel<<<(n_rows + 7) / 8, 256>>>(ps, zs, tgt, n_rows);

    // Launch final_kernel with programmatic stream serialization (PDL):
    // it begins scheduling immediately and blocks at
    // cudaGridDependencySynchronize() until accum_kernel completes.
    cudaLaunchConfig_t cfg = {};
    cfg.gridDim  = dim3(FBLK, 1, 1);
    cfg.blockDim = dim3(256, 1, 1);
    cfg.dynamicSmemBytes = 0;
    cfg.stream = 0;   // legacy default stream (captured by the harness)
    cudaLaunchAttribute attrs[1];
    attrs[0].id = cudaLaunchAttributeProgrammaticStreamSerialization;
    attrs[0].val.programmaticStreamSerializationAllowed = 1;
    cfg.attrs = attrs;
    cfg.numAttrs = 1;
    cudaLaunchKernelEx(&cfg, final_kernel, out);
}